// round 1
// baseline (speedup 1.0000x reference)
#include <cuda_runtime.h>
#include <cuda_bf16.h>
#include <cstdint>

// Problem constants (match reference_code)
#define NN   100000
#define EE   1600000
#define DIN  128
#define DH   128
#define DOUT 64

// ---------------------------------------------------------------------------
// Device scratch (no allocations allowed -> __device__ globals)
// ---------------------------------------------------------------------------
__device__ float g_deg  [NN];             // float degree
__device__ float g_agg1 [NN * DIN];       // layer-1 aggregation (128)
__device__ float g_h    [NN * DH];        // relu'd hidden (128)
__device__ float g_z    [NN * 128];       // [ y = h@W2_l.T (64) | y2 = h@W2_r.T (64) ]
__device__ float g_agg2 [NN * DOUT];      // layer-2 aggregation of y (64)
__device__ float g_Wt1  [256 * 128];      // transposed concat [W1_l ; W1_r] : Wt1[k][j]
__device__ float g_Wt2  [128 * 128];      // transposed concat [W2_l | W2_r] : Wt2[k][j]

// ---------------------------------------------------------------------------
// Zero scratch
// ---------------------------------------------------------------------------
__global__ void zero_kernel() {
    const float4 z = make_float4(0.f, 0.f, 0.f, 0.f);
    int tid = blockIdx.x * blockDim.x + threadIdx.x;
    int stride = gridDim.x * blockDim.x;
    for (int i = tid; i < NN / 4; i += stride)        ((float4*)g_deg )[i] = z;
    for (int i = tid; i < NN * (DIN  / 4); i += stride) ((float4*)g_agg1)[i] = z;
    for (int i = tid; i < NN * (DOUT / 4); i += stride) ((float4*)g_agg2)[i] = z;
}

// ---------------------------------------------------------------------------
// Pre-transpose weights into k-major layout (tiny; done every call)
// Wt1[k][j] : k<128 -> W1_l[j][k] (applied to mean), k>=128 -> W1_r[j][k-128] (applied to x)
// Wt2[k][j] : j<64  -> W2_l[j][k],  j>=64 -> W2_r[j-64][k]
// ---------------------------------------------------------------------------
__global__ void prep_weights(const float* __restrict__ W1l, const float* __restrict__ W1r,
                             const float* __restrict__ W2l, const float* __restrict__ W2r) {
    int idx = blockIdx.x * blockDim.x + threadIdx.x;
    if (idx < 256 * 128) {
        int k = idx >> 7, j = idx & 127;
        g_Wt1[idx] = (k < 128) ? W1l[j * 128 + k] : W1r[j * 128 + (k - 128)];
    }
    if (idx < 128 * 128) {
        int k = idx >> 7, j = idx & 127;
        g_Wt2[idx] = (j < 64) ? W2l[j * 128 + k] : W2r[(j - 64) * 128 + k];
    }
}

// ---------------------------------------------------------------------------
// Scatter layer 1: one warp per edge; 128 floats = 32 lanes x float4.
// Also accumulates degree (lane 0).
// ---------------------------------------------------------------------------
__global__ void scatter1(const float4* __restrict__ x4, const int* __restrict__ ei) {
    const int* __restrict__ src = ei;
    const int* __restrict__ dst = ei + EE;
    int gw   = (blockIdx.x * blockDim.x + threadIdx.x) >> 5;
    int lane = threadIdx.x & 31;
    int nw   = (gridDim.x * blockDim.x) >> 5;
    for (int e = gw; e < EE; e += nw) {
        int s = src[e];
        int d = dst[e];
        float4 v = x4[s * 32 + lane];
        const float* p = &g_agg1[(size_t)d * 128 + lane * 4];
        asm volatile("red.global.add.v4.f32 [%0], {%1, %2, %3, %4};"
                     :: "l"(p), "f"(v.x), "f"(v.y), "f"(v.z), "f"(v.w) : "memory");
        if (lane == 0) {
            asm volatile("red.global.add.f32 [%0], %1;"
                         :: "l"(&g_deg[d]), "f"(1.0f) : "memory");
        }
    }
}

// ---------------------------------------------------------------------------
// Scatter layer 2: y is 64 floats = 16 lanes x float4 -> half-warp per edge.
// ---------------------------------------------------------------------------
__global__ void scatter2(const int* __restrict__ ei) {
    const int* __restrict__ src = ei;
    const int* __restrict__ dst = ei + EE;
    int gw   = (blockIdx.x * blockDim.x + threadIdx.x) >> 5;
    int lane = threadIdx.x & 31;
    int half = lane >> 4;
    int l    = lane & 15;
    int nw   = (gridDim.x * blockDim.x) >> 5;
    for (int ep = gw; ep < EE / 2; ep += nw) {
        int e = ep * 2 + half;
        int s = src[e];
        int d = dst[e];
        float4 v = ((const float4*)g_z)[s * 32 + l];   // first 64 cols of z = y
        const float* p = &g_agg2[(size_t)d * 64 + l * 4];
        asm volatile("red.global.add.v4.f32 [%0], {%1, %2, %3, %4};"
                     :: "l"(p), "f"(v.x), "f"(v.y), "f"(v.z), "f"(v.w) : "memory");
    }
}

// ---------------------------------------------------------------------------
// Tiled fp32 GEMM. Block tile 64 rows x 128 cols, BK=64, 256 threads,
// thread tile 8x4. Weights pre-transposed (k-major) -> conflict-free smem.
//
// MODE 0 (layer 1): KTOT=256, A = [agg1*invdeg (k<128) | x (k>=128)],
//                   epilogue: +b1, relu -> g_h
// MODE 1 (layer 2): KTOT=128, A = g_h, epilogue: store -> g_z
// ---------------------------------------------------------------------------
template <int MODE>
__global__ __launch_bounds__(256, 2)
void gemm_kernel(const float* __restrict__ x, const float* __restrict__ b1) {
    constexpr int KTOT = (MODE == 0) ? 256 : 128;
    __shared__ float As[64][64];    // As[k][r]
    __shared__ float Ws[64][128];   // Ws[k][j]

    const int tid = threadIdx.x;
    const int tx  = tid & 31;       // 32 col-groups of 4
    const int ty  = tid >> 5;       // 8 row-groups of 8
    const int rowBase = blockIdx.x * 64;

    const float* __restrict__ Wt = (MODE == 0) ? g_Wt1 : g_Wt2;
    const float* __restrict__ A0 = (MODE == 0) ? g_agg1 : g_h;

    // Per-thread fixed A row for loading: r = tid & 63
    const int lr  = tid & 63;
    const int lgr = rowBase + lr;
    float inv = 1.0f;
    if (MODE == 0 && lgr < NN) inv = 1.0f / fmaxf(g_deg[lgr], 1.0f);

    float acc[8][4];
#pragma unroll
    for (int m = 0; m < 8; m++)
#pragma unroll
        for (int n = 0; n < 4; n++) acc[m][n] = 0.f;

    for (int kc = 0; kc < KTOT; kc += 64) {
        // ---- load A tile: 64 rows x 64 k = 1024 float4, 4 per thread ----
#pragma unroll
        for (int it = 0; it < 4; it++) {
            int s  = tid + it * 256;        // 0..1023
            int r  = s & 63;                // == lr (constant per thread)
            int kq = s >> 6;                // 0..15 (float4 index within chunk)
            float4 v = make_float4(0.f, 0.f, 0.f, 0.f);
            int gr = rowBase + r;
            if (gr < NN) {
                if (MODE == 0) {
                    if (kc < 128) {
                        v = ((const float4*)A0)[gr * 32 + (kc >> 2) + kq];
                        v.x *= inv; v.y *= inv; v.z *= inv; v.w *= inv;
                    } else {
                        v = ((const float4*)x)[gr * 32 + ((kc - 128) >> 2) + kq];
                    }
                } else {
                    v = ((const float4*)A0)[gr * 32 + (kc >> 2) + kq];
                }
            }
            int k0 = kq * 4;
            As[k0 + 0][r] = v.x;
            As[k0 + 1][r] = v.y;
            As[k0 + 2][r] = v.z;
            As[k0 + 3][r] = v.w;
        }
        // ---- load W tile: straight copy of Wt[kc..kc+63][0..127], 8 f4/thread ----
#pragma unroll
        for (int it = 0; it < 8; it++) {
            int s  = tid + it * 256;        // 0..2047
            int jq = s & 31;                // float4 along j
            int k  = s >> 5;                // 0..63
            float4 w = ((const float4*)Wt)[(kc + k) * 32 + jq];
            *(float4*)&Ws[k][jq * 4] = w;
        }
        __syncthreads();

        // ---- compute ----
#pragma unroll 16
        for (int k = 0; k < 64; k++) {
            float4 a0 = *(const float4*)&As[k][ty * 8];
            float4 a1 = *(const float4*)&As[k][ty * 8 + 4];
            float4 w  = *(const float4*)&Ws[k][tx * 4];
            float a[8] = {a0.x, a0.y, a0.z, a0.w, a1.x, a1.y, a1.z, a1.w};
#pragma unroll
            for (int m = 0; m < 8; m++) {
                acc[m][0] += a[m] * w.x;
                acc[m][1] += a[m] * w.y;
                acc[m][2] += a[m] * w.z;
                acc[m][3] += a[m] * w.w;
            }
        }
        __syncthreads();
    }

    // ---- epilogue ----
    if (MODE == 0) {
        float4 bb = ((const float4*)b1)[tx];
#pragma unroll
        for (int m = 0; m < 8; m++) {
            int gr = rowBase + ty * 8 + m;
            if (gr < NN) {
                float4 o;
                o.x = fmaxf(acc[m][0] + bb.x, 0.f);
                o.y = fmaxf(acc[m][1] + bb.y, 0.f);
                o.z = fmaxf(acc[m][2] + bb.z, 0.f);
                o.w = fmaxf(acc[m][3] + bb.w, 0.f);
                ((float4*)g_h)[gr * 32 + tx] = o;
            }
        }
    } else {
#pragma unroll
        for (int m = 0; m < 8; m++) {
            int gr = rowBase + ty * 8 + m;
            if (gr < NN) {
                float4 o = make_float4(acc[m][0], acc[m][1], acc[m][2], acc[m][3]);
                ((float4*)g_z)[gr * 32 + tx] = o;
            }
        }
    }
}

// ---------------------------------------------------------------------------
// Finalize: out[i][j] = agg2[i][j]/clip(deg,1) + b2[j] + z[i][64+j]
// ---------------------------------------------------------------------------
__global__ void finalize(float* __restrict__ out, const float* __restrict__ b2) {
    int tid = blockIdx.x * blockDim.x + threadIdx.x;
    int stride = gridDim.x * blockDim.x;
    for (int idx = tid; idx < NN * 16; idx += stride) {   // float4 over N*64
        int i  = idx >> 4;
        int jq = idx & 15;
        float inv = 1.0f / fmaxf(g_deg[i], 1.0f);
        float4 a  = ((const float4*)g_agg2)[idx];
        float4 y2 = ((const float4*)g_z)[i * 32 + 16 + jq];
        float4 bb = ((const float4*)b2)[jq];
        float4 o;
        o.x = a.x * inv + bb.x + y2.x;
        o.y = a.y * inv + bb.y + y2.y;
        o.z = a.z * inv + bb.z + y2.z;
        o.w = a.w * inv + bb.w + y2.w;
        ((float4*)out)[idx] = o;
    }
}

// ---------------------------------------------------------------------------
// Launch
// Inputs (metadata order): x, W1_l, W1_r, b1, W2_l, W2_r, b2, edge_index
// ---------------------------------------------------------------------------
extern "C" void kernel_launch(void* const* d_in, const int* in_sizes, int n_in,
                              void* d_out, int out_size) {
    const float* x   = (const float*)d_in[0];
    const float* W1l = (const float*)d_in[1];
    const float* W1r = (const float*)d_in[2];
    const float* b1  = (const float*)d_in[3];
    const float* W2l = (const float*)d_in[4];
    const float* W2r = (const float*)d_in[5];
    const float* b2  = (const float*)d_in[6];
    const int*   ei  = (const int*)d_in[7];
    float* out = (float*)d_out;

    zero_kernel<<<2048, 256>>>();
    prep_weights<<<128, 256>>>(W1l, W1r, W2l, W2r);
    scatter1<<<4096, 256>>>((const float4*)x, ei);
    gemm_kernel<0><<<(NN + 63) / 64, 256>>>(x, b1);
    gemm_kernel<1><<<(NN + 63) / 64, 256>>>(x, b1);
    scatter2<<<4096, 256>>>(ei);
    finalize<<<2048, 256>>>(out, b2);
}

// round 3
// speedup vs baseline: 1.0756x; 1.0756x over previous
#include <cuda_runtime.h>
#include <cuda_bf16.h>
#include <cstdint>

// Problem constants
#define NN   100000
#define EE   1600000

// ---------------------------------------------------------------------------
// Device scratch
// ---------------------------------------------------------------------------
__device__ float g_deg [NN];
__device__ float g_agg1[NN * 128];
__device__ __nv_bfloat16 g_h_hi[NN * 128];   // layer-1 output, pre-split bf16
__device__ __nv_bfloat16 g_h_lo[NN * 128];
__device__ float g_z   [NN * 128];           // [ y = h@W2_l.T | y2 = h@W2_r.T ]
__device__ float g_agg2[NN * 64];
// Pre-split weights, [n][k] k-contiguous (col-major for mma row.col)
__device__ __nv_bfloat16 g_B1hi[128 * 256];
__device__ __nv_bfloat16 g_B1lo[128 * 256];
__device__ __nv_bfloat16 g_B2hi[128 * 128];
__device__ __nv_bfloat16 g_B2lo[128 * 128];

// ---------------------------------------------------------------------------
// Helpers
// ---------------------------------------------------------------------------
__device__ __forceinline__ uint32_t smem_u32(const void* p) {
    uint32_t a;
    asm("{ .reg .u64 t; cvta.to.shared.u64 t, %1; cvt.u32.u64 %0, t; }" : "=r"(a) : "l"(p));
    return a;
}
#define SWZ(o) ((o) ^ (((o) >> 3) & 0x70u))

__device__ __forceinline__ void split2(float v, __nv_bfloat16& h, __nv_bfloat16& l) {
    h = __float2bfloat16(v);
    l = __float2bfloat16(v - __bfloat162float(h));
}
__device__ __forceinline__ uint32_t pack_bf(__nv_bfloat16 a, __nv_bfloat16 b) {
    __nv_bfloat162 t = __halves2bfloat162(a, b);
    return *(uint32_t*)&t;
}

#define LDSM4(r, a) \
    asm volatile("ldmatrix.sync.aligned.m8n8.x4.shared.b16 {%0,%1,%2,%3}, [%4];" \
        : "=r"((r)[0]), "=r"((r)[1]), "=r"((r)[2]), "=r"((r)[3]) : "r"(a))

__device__ __forceinline__ void mma_bf16(float* d, const uint32_t* a, uint32_t b0, uint32_t b1) {
    asm volatile("mma.sync.aligned.m16n8k16.row.col.f32.bf16.bf16.f32 "
                 "{%0,%1,%2,%3}, {%4,%5,%6,%7}, {%8,%9}, {%0,%1,%2,%3};"
                 : "+f"(d[0]), "+f"(d[1]), "+f"(d[2]), "+f"(d[3])
                 : "r"(a[0]), "r"(a[1]), "r"(a[2]), "r"(a[3]), "r"(b0), "r"(b1));
}

// ---------------------------------------------------------------------------
// Zero scratch
// ---------------------------------------------------------------------------
__global__ void zero_kernel() {
    const float4 z = make_float4(0.f, 0.f, 0.f, 0.f);
    int tid = blockIdx.x * blockDim.x + threadIdx.x;
    int stride = gridDim.x * blockDim.x;
    for (int i = tid; i < NN / 4; i += stride)      ((float4*)g_deg )[i] = z;
    for (int i = tid; i < NN * 32; i += stride)     ((float4*)g_agg1)[i] = z;
    for (int i = tid; i < NN * 16; i += stride)     ((float4*)g_agg2)[i] = z;
}

// ---------------------------------------------------------------------------
// Pre-split weights into bf16 hi/lo planes, [n][k] layout.
// B1[n][k] (128x256): k<128 -> W1_l[n][k], else W1_r[n][k-128]
// B2[n][k] (128x128): n<64  -> W2_l[n][k], else W2_r[n-64][k]
// ---------------------------------------------------------------------------
__global__ void prep_weights(const float* __restrict__ W1l, const float* __restrict__ W1r,
                             const float* __restrict__ W2l, const float* __restrict__ W2r) {
    int idx = blockIdx.x * blockDim.x + threadIdx.x;
    if (idx < 128 * 256) {
        int n = idx >> 8, k = idx & 255;
        float v = (k < 128) ? W1l[n * 128 + k] : W1r[n * 128 + (k - 128)];
        __nv_bfloat16 h, l; split2(v, h, l);
        g_B1hi[idx] = h; g_B1lo[idx] = l;
    }
    int idx2 = idx - 128 * 256;
    if (idx2 >= 0 && idx2 < 128 * 128) {
        int n = idx2 >> 7, k = idx2 & 127;
        float v = (n < 64) ? W2l[n * 128 + k] : W2r[(n - 64) * 128 + k];
        __nv_bfloat16 h, l; split2(v, h, l);
        g_B2hi[idx2] = h; g_B2lo[idx2] = l;
    }
}

// ---------------------------------------------------------------------------
// Scatters
// ---------------------------------------------------------------------------
__global__ void scatter1(const float4* __restrict__ x4, const int* __restrict__ ei) {
    const int* __restrict__ src = ei;
    const int* __restrict__ dst = ei + EE;
    int gw   = (blockIdx.x * blockDim.x + threadIdx.x) >> 5;
    int lane = threadIdx.x & 31;
    int nw   = (gridDim.x * blockDim.x) >> 5;
    for (int e = gw; e < EE; e += nw) {
        int s = src[e];
        int d = dst[e];
        float4 v = x4[s * 32 + lane];
        const float* p = &g_agg1[(size_t)d * 128 + lane * 4];
        asm volatile("red.global.add.v4.f32 [%0], {%1, %2, %3, %4};"
                     :: "l"(p), "f"(v.x), "f"(v.y), "f"(v.z), "f"(v.w) : "memory");
        if (lane == 0) {
            asm volatile("red.global.add.f32 [%0], %1;"
                         :: "l"(&g_deg[d]), "f"(1.0f) : "memory");
        }
    }
}

__global__ void scatter2(const int* __restrict__ ei) {
    const int* __restrict__ src = ei;
    const int* __restrict__ dst = ei + EE;
    int gw   = (blockIdx.x * blockDim.x + threadIdx.x) >> 5;
    int lane = threadIdx.x & 31;
    int half = lane >> 4;
    int l    = lane & 15;
    int nw   = (gridDim.x * blockDim.x) >> 5;
    for (int ep = gw; ep < EE / 2; ep += nw) {
        int e = ep * 2 + half;
        int s = src[e];
        int d = dst[e];
        float4 v = ((const float4*)g_z)[s * 32 + l];
        const float* p = &g_agg2[(size_t)d * 64 + l * 4];
        asm volatile("red.global.add.v4.f32 [%0], {%1, %2, %3, %4};"
                     :: "l"(p), "f"(v.x), "f"(v.y), "f"(v.z), "f"(v.w) : "memory");
    }
}

// ---------------------------------------------------------------------------
// mma.sync split-bf16 GEMM. CTA tile 128(M)x128(N); 8 warps: wm=wid&3 (M32),
// wn=wid>>2 (N64). K chunked by 64. D = Ah*Bh + Al*Bh + Ah*Bl (fp32 acc).
//
// MODE 0: A = [mean(agg1) | x] (K=256, split on the fly), B = B1.
//         epilogue: +b1, relu, split -> g_h_hi/g_h_lo
// MODE 1: A = g_h (pre-split, K=128), B = B2. epilogue: raw fp32 -> g_z
// ---------------------------------------------------------------------------
template <int MODE>
__global__ __launch_bounds__(256, 1)
void gemm_mma(const float* __restrict__ x, const float* __restrict__ b1) {
    constexpr int KTOT = (MODE == 0) ? 256 : 128;
    constexpr int BCH  = KTOT / 64;              // K chunks
    constexpr int SM_A = 2 * BCH * 16384;        // after B hi[BCH] + B lo[BCH]
    extern __shared__ char sm[];
    const uint32_t sb = smem_u32(sm);
    const int tid = threadIdx.x, wid = tid >> 5, lane = tid & 31;
    const int rowBase = blockIdx.x * 128;
    const int wm = wid & 3, wn = wid >> 2;
    const int sub = lane >> 3, lr = lane & 7;

    // ---- Load resident B (all chunks, hi+lo), swizzled 128B rows of 64 bf16 ----
    {
        const uint4* Bh4 = (const uint4*)((MODE == 0) ? g_B1hi : g_B2hi);
        const uint4* Bl4 = (const uint4*)((MODE == 0) ? g_B1lo : g_B2lo);
        const int NU = 128 * KTOT / 8;
        for (int u = tid; u < NU; u += 256) {
            int n  = (MODE == 0) ? (u >> 5) : (u >> 4);
            int k0 = ((MODE == 0) ? (u & 31) : (u & 15)) * 8;
            int c = k0 >> 6, kin = k0 & 63;
            uint32_t off = SWZ((uint32_t)(n * 128 + kin * 2));
            *(uint4*)(sm + c * 16384 + off)           = Bh4[u];
            *(uint4*)(sm + (BCH + c) * 16384 + off)   = Bl4[u];
        }
    }

    float acc[2][8][4];
#pragma unroll
    for (int i = 0; i < 2; i++)
#pragma unroll
        for (int j = 0; j < 8; j++)
#pragma unroll
            for (int r = 0; r < 4; r++) acc[i][j][r] = 0.f;

    for (int c = 0; c < BCH; c++) {
        __syncthreads();   // protect A buffer reuse (and B on first iter)
        // ---- Load A chunk (128 rows x 64 k), hi+lo planes ----
#pragma unroll
        for (int it = 0; it < 8; it++) {
            int s = it * 256 + tid;
            int row = s >> 4, q = s & 15;
            int gr = rowBase + row;
            uint2 uh = make_uint2(0u, 0u), ul = make_uint2(0u, 0u);
            if (gr < NN) {
                if (MODE == 1) {
                    uh = ((const uint2*)g_h_hi)[gr * 32 + c * 16 + q];
                    ul = ((const uint2*)g_h_lo)[gr * 32 + c * 16 + q];
                } else {
                    float4 v;
                    if (c < 2) {
                        v = ((const float4*)g_agg1)[gr * 32 + c * 16 + q];
                        float iv = 1.0f / fmaxf(g_deg[gr], 1.0f);
                        v.x *= iv; v.y *= iv; v.z *= iv; v.w *= iv;
                    } else {
                        v = ((const float4*)x)[gr * 32 + (c - 2) * 16 + q];
                    }
                    __nv_bfloat16 h0, h1, h2, h3, l0, l1, l2, l3;
                    split2(v.x, h0, l0); split2(v.y, h1, l1);
                    split2(v.z, h2, l2); split2(v.w, h3, l3);
                    uh.x = pack_bf(h0, h1); uh.y = pack_bf(h2, h3);
                    ul.x = pack_bf(l0, l1); ul.y = pack_bf(l2, l3);
                }
            }
            uint32_t off = SWZ((uint32_t)(row * 128 + q * 8));
            *(uint2*)(sm + SM_A + off)         = uh;
            *(uint2*)(sm + SM_A + 16384 + off) = ul;
        }
        __syncthreads();

        // ---- Compute: 4 k16 steps ----
#pragma unroll
        for (int kk = 0; kk < 4; kk++) {
            uint32_t ah[2][4], al[2][4];
#pragma unroll
            for (int mi = 0; mi < 2; mi++) {
                int row = wm * 32 + mi * 16 + (sub & 1) * 8 + lr;
                int kb  = kk * 32 + (sub >> 1) * 16;
                uint32_t off = SWZ((uint32_t)(row * 128 + kb));
                LDSM4(ah[mi], sb + SM_A + off);
                LDSM4(al[mi], sb + SM_A + 16384 + off);
            }
#pragma unroll
            for (int p = 0; p < 4; p++) {
                int nr = wn * 64 + p * 16 + (sub >> 1) * 8 + lr;
                int kb = kk * 32 + (sub & 1) * 16;
                uint32_t off = SWZ((uint32_t)(nr * 128 + kb));
                uint32_t bh[4], bl[4];
                LDSM4(bh, sb + c * 16384 + off);
                LDSM4(bl, sb + (BCH + c) * 16384 + off);
#pragma unroll
                for (int mi = 0; mi < 2; mi++) {
#pragma unroll
                    for (int h = 0; h < 2; h++) {
                        float* d = acc[mi][p * 2 + h];
                        mma_bf16(d, ah[mi], bh[2 * h], bh[2 * h + 1]);
                        mma_bf16(d, al[mi], bh[2 * h], bh[2 * h + 1]);
                        mma_bf16(d, ah[mi], bl[2 * h], bl[2 * h + 1]);
                    }
                }
            }
        }
    }

    // ---- Epilogue ----
#pragma unroll
    for (int mi = 0; mi < 2; mi++) {
        int r0 = rowBase + wm * 32 + mi * 16 + (lane >> 2);
#pragma unroll
        for (int p = 0; p < 4; p++) {
#pragma unroll
            for (int h = 0; h < 2; h++) {
                int col = wn * 64 + p * 16 + h * 8 + 2 * (lane & 3);
                float* d = acc[mi][p * 2 + h];
#pragma unroll
                for (int half = 0; half < 2; half++) {   // rows r0, r0+8
                    int gr = r0 + half * 8;
                    if (gr < NN) {
                        float v0 = d[half * 2 + 0];
                        float v1 = d[half * 2 + 1];
                        if (MODE == 0) {
                            v0 = fmaxf(v0 + b1[col], 0.f);
                            v1 = fmaxf(v1 + b1[col + 1], 0.f);
                            __nv_bfloat16 h0, l0, h1, l1;
                            split2(v0, h0, l0); split2(v1, h1, l1);
                            *(uint32_t*)(g_h_hi + gr * 128 + col) = pack_bf(h0, h1);
                            *(uint32_t*)(g_h_lo + gr * 128 + col) = pack_bf(l0, l1);
                        } else {
                            *(float2*)(g_z + gr * 128 + col) = make_float2(v0, v1);
                        }
                    }
                }
            }
        }
    }
}

// ---------------------------------------------------------------------------
// Finalize: out[i][j] = agg2[i][j]/clip(deg,1) + b2[j] + z[i][64+j]
// ---------------------------------------------------------------------------
__global__ void finalize(float* __restrict__ out, const float* __restrict__ b2) {
    int tid = blockIdx.x * blockDim.x + threadIdx.x;
    int stride = gridDim.x * blockDim.x;
    for (int idx = tid; idx < NN * 16; idx += stride) {
        int i  = idx >> 4;
        int jq = idx & 15;
        float inv = 1.0f / fmaxf(g_deg[i], 1.0f);
        float4 a  = ((const float4*)g_agg2)[idx];
        float4 y2 = ((const float4*)g_z)[i * 32 + 16 + jq];
        float4 bb = ((const float4*)b2)[jq];
        float4 o;
        o.x = a.x * inv + bb.x + y2.x;
        o.y = a.y * inv + bb.y + y2.y;
        o.z = a.z * inv + bb.z + y2.z;
        o.w = a.w * inv + bb.w + y2.w;
        ((float4*)out)[idx] = o;
    }
}

// ---------------------------------------------------------------------------
// Launch. Inputs: x, W1_l, W1_r, b1, W2_l, W2_r, b2, edge_index
// ---------------------------------------------------------------------------
extern "C" void kernel_launch(void* const* d_in, const int* in_sizes, int n_in,
                              void* d_out, int out_size) {
    const float* x   = (const float*)d_in[0];
    const float* W1l = (const float*)d_in[1];
    const float* W1r = (const float*)d_in[2];
    const float* b1  = (const float*)d_in[3];
    const float* W2l = (const float*)d_in[4];
    const float* W2r = (const float*)d_in[5];
    const float* b2  = (const float*)d_in[6];
    const int*   ei  = (const int*)d_in[7];
    float* out = (float*)d_out;

    const int SMEM0 = 2 * 4 * 16384 + 2 * 16384;  // 160 KB
    const int SMEM1 = 2 * 2 * 16384 + 2 * 16384;  // 96 KB
    cudaFuncSetAttribute(gemm_mma<0>, cudaFuncAttributeMaxDynamicSharedMemorySize, SMEM0);
    cudaFuncSetAttribute(gemm_mma<1>, cudaFuncAttributeMaxDynamicSharedMemorySize, SMEM1);

    const int NBLK = (NN + 127) / 128;  // 782

    zero_kernel<<<2048, 256>>>();
    prep_weights<<<192, 256>>>(W1l, W1r, W2l, W2r);
    scatter1<<<4096, 256>>>((const float4*)x, ei);
    gemm_mma<0><<<NBLK, 256, SMEM0>>>(x, b1);
    gemm_mma<1><<<NBLK, 256, SMEM1>>>(x, b1);
    scatter2<<<4096, 256>>>(ei);
    finalize<<<2048, 256>>>(out, b2);
}

// round 4
// speedup vs baseline: 1.2942x; 1.2032x over previous
#include <cuda_runtime.h>
#include <cuda_bf16.h>
#include <cstdint>

// Problem constants
#define NN   100000
#define EE   1600000
#define NPAD 100096              // 782 * 128 (padded rows; pads stay zero)

// ---------------------------------------------------------------------------
// Device scratch
// ---------------------------------------------------------------------------
__device__ float g_deg [NN];
__device__ float g_agg1[NN * 128];
__device__ __nv_bfloat16 g_A1hi[NPAD * 256];  // [mean(agg1) | x] pre-split
__device__ __nv_bfloat16 g_A1lo[NPAD * 256];
__device__ __nv_bfloat16 g_h_hi[NPAD * 128];  // layer-1 output pre-split
__device__ __nv_bfloat16 g_h_lo[NPAD * 128];
__device__ float g_z   [NN * 128];            // [ y (64) | y2 (64) ]
__device__ float g_agg2[NN * 64];
// Pre-split weights, [n][k] k-contiguous
__device__ __nv_bfloat16 g_B1hi[128 * 256];
__device__ __nv_bfloat16 g_B1lo[128 * 256];
__device__ __nv_bfloat16 g_B2hi[128 * 128];
__device__ __nv_bfloat16 g_B2lo[128 * 128];

// ---------------------------------------------------------------------------
// Helpers
// ---------------------------------------------------------------------------
__device__ __forceinline__ uint32_t smem_u32(const void* p) {
    uint32_t a;
    asm("{ .reg .u64 t; cvta.to.shared.u64 t, %1; cvt.u32.u64 %0, t; }" : "=r"(a) : "l"(p));
    return a;
}
#define SWZ(o) ((o) ^ (((o) >> 3) & 0x70u))

__device__ __forceinline__ void split2(float v, __nv_bfloat16& h, __nv_bfloat16& l) {
    h = __float2bfloat16(v);
    l = __float2bfloat16(v - __bfloat162float(h));
}
__device__ __forceinline__ uint32_t pack_bf(__nv_bfloat16 a, __nv_bfloat16 b) {
    __nv_bfloat162 t = __halves2bfloat162(a, b);
    return *(uint32_t*)&t;
}

#define LDSM4(r, a) \
    asm volatile("ldmatrix.sync.aligned.m8n8.x4.shared.b16 {%0,%1,%2,%3}, [%4];" \
        : "=r"((r)[0]), "=r"((r)[1]), "=r"((r)[2]), "=r"((r)[3]) : "r"(a))

__device__ __forceinline__ void mma_bf16(float* d, const uint32_t* a, uint32_t b0, uint32_t b1) {
    asm volatile("mma.sync.aligned.m16n8k16.row.col.f32.bf16.bf16.f32 "
                 "{%0,%1,%2,%3}, {%4,%5,%6,%7}, {%8,%9}, {%0,%1,%2,%3};"
                 : "+f"(d[0]), "+f"(d[1]), "+f"(d[2]), "+f"(d[3])
                 : "r"(a[0]), "r"(a[1]), "r"(a[2]), "r"(a[3]), "r"(b0), "r"(b1));
}

__device__ __forceinline__ void cp16(uint32_t s, const void* g) {
    asm volatile("cp.async.cg.shared.global [%0], [%1], 16;" :: "r"(s), "l"(g));
}
#define CP_COMMIT() asm volatile("cp.async.commit_group;" ::: "memory")
template <int N>
__device__ __forceinline__ void cp_wait() {
    asm volatile("cp.async.wait_group %0;" :: "n"(N) : "memory");
}

// ---------------------------------------------------------------------------
// Zero scratch
// ---------------------------------------------------------------------------
__global__ void zero_kernel() {
    const float4 z = make_float4(0.f, 0.f, 0.f, 0.f);
    int tid = blockIdx.x * blockDim.x + threadIdx.x;
    int stride = gridDim.x * blockDim.x;
    for (int i = tid; i < NN / 4; i += stride)  ((float4*)g_deg )[i] = z;
    for (int i = tid; i < NN * 32; i += stride) ((float4*)g_agg1)[i] = z;
    for (int i = tid; i < NN * 16; i += stride) ((float4*)g_agg2)[i] = z;
}

// ---------------------------------------------------------------------------
// Pre-split weights, [n][k] layout.
// ---------------------------------------------------------------------------
__global__ void prep_weights(const float* __restrict__ W1l, const float* __restrict__ W1r,
                             const float* __restrict__ W2l, const float* __restrict__ W2r) {
    int idx = blockIdx.x * blockDim.x + threadIdx.x;
    if (idx < 128 * 256) {
        int n = idx >> 8, k = idx & 255;
        float v = (k < 128) ? W1l[n * 128 + k] : W1r[n * 128 + (k - 128)];
        __nv_bfloat16 h, l; split2(v, h, l);
        g_B1hi[idx] = h; g_B1lo[idx] = l;
    }
    int idx2 = idx - 128 * 256;
    if (idx2 >= 0 && idx2 < 128 * 128) {
        int n = idx2 >> 7, k = idx2 & 127;
        float v = (n < 64) ? W2l[n * 128 + k] : W2r[(n - 64) * 128 + k];
        __nv_bfloat16 h, l; split2(v, h, l);
        g_B2hi[idx2] = h; g_B2lo[idx2] = l;
    }
}

// ---------------------------------------------------------------------------
// Scatters
// ---------------------------------------------------------------------------
__global__ void scatter1(const float4* __restrict__ x4, const int* __restrict__ ei) {
    const int* __restrict__ src = ei;
    const int* __restrict__ dst = ei + EE;
    int gw   = (blockIdx.x * blockDim.x + threadIdx.x) >> 5;
    int lane = threadIdx.x & 31;
    int nw   = (gridDim.x * blockDim.x) >> 5;
    for (int e = gw; e < EE; e += nw) {
        int s = src[e];
        int d = dst[e];
        float4 v = x4[s * 32 + lane];
        const float* p = &g_agg1[(size_t)d * 128 + lane * 4];
        asm volatile("red.global.add.v4.f32 [%0], {%1, %2, %3, %4};"
                     :: "l"(p), "f"(v.x), "f"(v.y), "f"(v.z), "f"(v.w) : "memory");
        if (lane == 0) {
            asm volatile("red.global.add.f32 [%0], %1;"
                         :: "l"(&g_deg[d]), "f"(1.0f) : "memory");
        }
    }
}

__global__ void scatter2(const int* __restrict__ ei) {
    const int* __restrict__ src = ei;
    const int* __restrict__ dst = ei + EE;
    int gw   = (blockIdx.x * blockDim.x + threadIdx.x) >> 5;
    int lane = threadIdx.x & 31;
    int half = lane >> 4;
    int l    = lane & 15;
    int nw   = (gridDim.x * blockDim.x) >> 5;
    for (int ep = gw; ep < EE / 2; ep += nw) {
        int e = ep * 2 + half;
        int s = src[e];
        int d = dst[e];
        float4 v = ((const float4*)g_z)[s * 32 + l];
        const float* p = &g_agg2[(size_t)d * 64 + l * 4];
        asm volatile("red.global.add.v4.f32 [%0], {%1, %2, %3, %4};"
                     :: "l"(p), "f"(v.x), "f"(v.y), "f"(v.z), "f"(v.w) : "memory");
    }
}

// ---------------------------------------------------------------------------
// split_A1: A1[i][k] = (k<128 ? agg1[i][k]/clip(deg,1) : x[i][k-128]) split hi/lo
// ---------------------------------------------------------------------------
__global__ void split_A1(const float4* __restrict__ x4) {
    int tid = blockIdx.x * blockDim.x + threadIdx.x;
    int stride = gridDim.x * blockDim.x;
    for (int idx = tid; idx < NN * 64; idx += stride) {
        int i = idx >> 6, q = idx & 63;
        float4 v;
        if (q < 32) {
            v = ((const float4*)g_agg1)[i * 32 + q];
            float inv = 1.0f / fmaxf(g_deg[i], 1.0f);
            v.x *= inv; v.y *= inv; v.z *= inv; v.w *= inv;
        } else {
            v = x4[i * 32 + (q - 32)];
        }
        __nv_bfloat16 h0, h1, h2, h3, l0, l1, l2, l3;
        split2(v.x, h0, l0); split2(v.y, h1, l1);
        split2(v.z, h2, l2); split2(v.w, h3, l3);
        uint2 uh, ul;
        uh.x = pack_bf(h0, h1); uh.y = pack_bf(h2, h3);
        ul.x = pack_bf(l0, l1); ul.y = pack_bf(l2, l3);
        ((uint2*)g_A1hi)[(size_t)i * 64 + q] = uh;
        ((uint2*)g_A1lo)[(size_t)i * 64 + q] = ul;
    }
}

// ---------------------------------------------------------------------------
// mma.sync split-bf16 GEMM. 512 threads, CTA tile 128(M)x128(N), warp 32x32.
// cp.async double-buffered K chunks of 64 (A hi/lo + B hi/lo per buffer).
// D = Ah*Bh + Al*Bh + Ah*Bl (fp32 acc).
// MODE 0: A = A1 planes (K=256), B = B1; epilogue +b1, relu, split -> h planes
// MODE 1: A = h planes (K=128), B = B2; epilogue raw fp32 -> g_z
// ---------------------------------------------------------------------------
template <int MODE>
__global__ __launch_bounds__(512, 1)
void gemm_mma(const float* __restrict__ b1) {
    constexpr int KTOT = (MODE == 0) ? 256 : 128;
    constexpr int CH   = KTOT / 64;
    constexpr int A_HI = 0, A_LO = 16384, B_HI = 32768, B_LO = 49152;
    extern __shared__ char sm[];
    const uint32_t sb = smem_u32(sm);
    const int tid = threadIdx.x, wid = tid >> 5, lane = tid & 31;
    const int rowBase = blockIdx.x * 128;
    const int wm = wid & 3, wn = wid >> 2;           // 4x4 warp grid
    const int sub = lane >> 3, lr = lane & 7;

    const __nv_bfloat16* __restrict__ Ah = (MODE == 0) ? g_A1hi : g_h_hi;
    const __nv_bfloat16* __restrict__ Al = (MODE == 0) ? g_A1lo : g_h_lo;
    const __nv_bfloat16* __restrict__ Bh = (MODE == 0) ? g_B1hi : g_B2hi;
    const __nv_bfloat16* __restrict__ Bl = (MODE == 0) ? g_B1lo : g_B2lo;

    // per-thread load slots: idx in [0,1024): row=idx>>3, seg=idx&7 (16B)
    auto load_chunk = [&](int c, int buf) {
        const uint32_t bb = sb + buf * 65536;
#pragma unroll
        for (int it = 0; it < 2; it++) {
            int idx = it * 512 + tid;
            int row = idx >> 3, seg = idx & 7;
            uint32_t doff = SWZ((uint32_t)(row * 128 + seg * 16));
            size_t ga = (size_t)(rowBase + row) * KTOT + c * 64 + seg * 8;
            cp16(bb + A_HI + doff, Ah + ga);
            cp16(bb + A_LO + doff, Al + ga);
            size_t gb = (size_t)row * KTOT + c * 64 + seg * 8;
            cp16(bb + B_HI + doff, Bh + gb);
            cp16(bb + B_LO + doff, Bl + gb);
        }
    };

    float acc[2][4][4];
#pragma unroll
    for (int i = 0; i < 2; i++)
#pragma unroll
        for (int j = 0; j < 4; j++)
#pragma unroll
            for (int r = 0; r < 4; r++) acc[i][j][r] = 0.f;

    load_chunk(0, 0); CP_COMMIT();

    for (int c = 0; c < CH; c++) {
        if (c + 1 < CH) { load_chunk(c + 1, (c + 1) & 1); CP_COMMIT(); cp_wait<1>(); }
        else            { cp_wait<0>(); }
        __syncthreads();

        const uint32_t bb = sb + (c & 1) * 65536;
#pragma unroll
        for (int kk = 0; kk < 4; kk++) {
            uint32_t ah[2][4], al[2][4];
#pragma unroll
            for (int mi = 0; mi < 2; mi++) {
                int row = wm * 32 + mi * 16 + (sub & 1) * 8 + lr;
                int kb  = kk * 32 + (sub >> 1) * 16;
                uint32_t off = SWZ((uint32_t)(row * 128 + kb));
                LDSM4(ah[mi], bb + A_HI + off);
                LDSM4(al[mi], bb + A_LO + off);
            }
#pragma unroll
            for (int p = 0; p < 2; p++) {
                int nr = wn * 32 + p * 16 + (sub >> 1) * 8 + lr;
                int kb = kk * 32 + (sub & 1) * 16;
                uint32_t off = SWZ((uint32_t)(nr * 128 + kb));
                uint32_t bh[4], bl[4];
                LDSM4(bh, bb + B_HI + off);
                LDSM4(bl, bb + B_LO + off);
#pragma unroll
                for (int mi = 0; mi < 2; mi++) {
#pragma unroll
                    for (int h = 0; h < 2; h++) {
                        float* d = acc[mi][p * 2 + h];
                        mma_bf16(d, ah[mi], bh[2 * h], bh[2 * h + 1]);
                        mma_bf16(d, al[mi], bh[2 * h], bh[2 * h + 1]);
                        mma_bf16(d, ah[mi], bl[2 * h], bl[2 * h + 1]);
                    }
                }
            }
        }
        __syncthreads();
    }

    // ---- Epilogue ----
#pragma unroll
    for (int mi = 0; mi < 2; mi++) {
        int r0 = rowBase + wm * 32 + mi * 16 + (lane >> 2);
#pragma unroll
        for (int p = 0; p < 2; p++) {
#pragma unroll
            for (int h = 0; h < 2; h++) {
                int col = wn * 32 + p * 16 + h * 8 + 2 * (lane & 3);
                float* d = acc[mi][p * 2 + h];
#pragma unroll
                for (int half = 0; half < 2; half++) {
                    int gr = r0 + half * 8;
                    if (gr < NN) {
                        float v0 = d[half * 2 + 0];
                        float v1 = d[half * 2 + 1];
                        if (MODE == 0) {
                            v0 = fmaxf(v0 + b1[col], 0.f);
                            v1 = fmaxf(v1 + b1[col + 1], 0.f);
                            __nv_bfloat16 h0, l0, h1, l1;
                            split2(v0, h0, l0); split2(v1, h1, l1);
                            *(uint32_t*)(g_h_hi + (size_t)gr * 128 + col) = pack_bf(h0, h1);
                            *(uint32_t*)(g_h_lo + (size_t)gr * 128 + col) = pack_bf(l0, l1);
                        } else {
                            *(float2*)(g_z + (size_t)gr * 128 + col) = make_float2(v0, v1);
                        }
                    }
                }
            }
        }
    }
}

// ---------------------------------------------------------------------------
// Finalize: out[i][j] = agg2[i][j]/clip(deg,1) + b2[j] + z[i][64+j]
// ---------------------------------------------------------------------------
__global__ void finalize(float* __restrict__ out, const float* __restrict__ b2) {
    int tid = blockIdx.x * blockDim.x + threadIdx.x;
    int stride = gridDim.x * blockDim.x;
    for (int idx = tid; idx < NN * 16; idx += stride) {
        int i  = idx >> 4;
        int jq = idx & 15;
        float inv = 1.0f / fmaxf(g_deg[i], 1.0f);
        float4 a  = ((const float4*)g_agg2)[idx];
        float4 y2 = ((const float4*)g_z)[i * 32 + 16 + jq];
        float4 bb = ((const float4*)b2)[jq];
        float4 o;
        o.x = a.x * inv + bb.x + y2.x;
        o.y = a.y * inv + bb.y + y2.y;
        o.z = a.z * inv + bb.z + y2.z;
        o.w = a.w * inv + bb.w + y2.w;
        ((float4*)out)[idx] = o;
    }
}

// ---------------------------------------------------------------------------
// Launch. Inputs: x, W1_l, W1_r, b1, W2_l, W2_r, b2, edge_index
// ---------------------------------------------------------------------------
extern "C" void kernel_launch(void* const* d_in, const int* in_sizes, int n_in,
                              void* d_out, int out_size) {
    const float* x   = (const float*)d_in[0];
    const float* W1l = (const float*)d_in[1];
    const float* W1r = (const float*)d_in[2];
    const float* b1  = (const float*)d_in[3];
    const float* W2l = (const float*)d_in[4];
    const float* W2r = (const float*)d_in[5];
    const float* b2  = (const float*)d_in[6];
    const int*   ei  = (const int*)d_in[7];
    float* out = (float*)d_out;

    const int SMEM = 2 * 65536;  // 128 KB
    cudaFuncSetAttribute(gemm_mma<0>, cudaFuncAttributeMaxDynamicSharedMemorySize, SMEM);
    cudaFuncSetAttribute(gemm_mma<1>, cudaFuncAttributeMaxDynamicSharedMemorySize, SMEM);

    const int NBLK = (NN + 127) / 128;  // 782

    zero_kernel<<<2048, 256>>>();
    prep_weights<<<192, 256>>>(W1l, W1r, W2l, W2r);
    scatter1<<<4096, 256>>>((const float4*)x, ei);
    split_A1<<<4096, 256>>>((const float4*)x);
    gemm_mma<0><<<NBLK, 512, SMEM>>>(b1);
    gemm_mma<1><<<NBLK, 512, SMEM>>>(b1);
    scatter2<<<4096, 256>>>(ei);
    finalize<<<2048, 256>>>(out, b2);
}

// round 5
// speedup vs baseline: 2.0999x; 1.6225x over previous
#include <cuda_runtime.h>
#include <cuda_bf16.h>
#include <cstdint>

// Problem constants
#define NN   100000
#define EE   1600000
#define NPAD 100096              // 782 * 128 (padded rows; pads stay zero)
#define NCHUNK 98                // ceil(NN / 1024)

// ---------------------------------------------------------------------------
// Device scratch
// ---------------------------------------------------------------------------
__device__ int g_cnt[NN];                     // degree (histogram)
__device__ int g_off[NN];                     // CSR exclusive offsets
__device__ int g_pos[NN];                     // fill cursors
__device__ int g_csr[EE];                     // dst-grouped src indices
__device__ int g_chunksum[NCHUNK];
__device__ __nv_bfloat16 g_A1hi[NPAD * 256];  // [mean(agg1) | x] pre-split
__device__ __nv_bfloat16 g_A1lo[NPAD * 256];
__device__ __nv_bfloat16 g_h_hi[NPAD * 128];  // layer-1 output pre-split
__device__ __nv_bfloat16 g_h_lo[NPAD * 128];
__device__ float g_z[NN * 128];               // [ y (64) | y2 (64) ]
// Pre-split weights, [n][k] k-contiguous
__device__ __nv_bfloat16 g_B1hi[128 * 256];
__device__ __nv_bfloat16 g_B1lo[128 * 256];
__device__ __nv_bfloat16 g_B2hi[128 * 128];
__device__ __nv_bfloat16 g_B2lo[128 * 128];

// ---------------------------------------------------------------------------
// Helpers
// ---------------------------------------------------------------------------
__device__ __forceinline__ uint32_t smem_u32(const void* p) {
    uint32_t a;
    asm("{ .reg .u64 t; cvta.to.shared.u64 t, %1; cvt.u32.u64 %0, t; }" : "=r"(a) : "l"(p));
    return a;
}
#define SWZ(o) ((o) ^ (((o) >> 3) & 0x70u))

__device__ __forceinline__ void split2(float v, __nv_bfloat16& h, __nv_bfloat16& l) {
    h = __float2bfloat16(v);
    l = __float2bfloat16(v - __bfloat162float(h));
}
__device__ __forceinline__ uint32_t pack_bf(__nv_bfloat16 a, __nv_bfloat16 b) {
    __nv_bfloat162 t = __halves2bfloat162(a, b);
    return *(uint32_t*)&t;
}

#define LDSM4(r, a) \
    asm volatile("ldmatrix.sync.aligned.m8n8.x4.shared.b16 {%0,%1,%2,%3}, [%4];" \
        : "=r"((r)[0]), "=r"((r)[1]), "=r"((r)[2]), "=r"((r)[3]) : "r"(a))

__device__ __forceinline__ void mma_bf16(float* d, const uint32_t* a, uint32_t b0, uint32_t b1) {
    asm volatile("mma.sync.aligned.m16n8k16.row.col.f32.bf16.bf16.f32 "
                 "{%0,%1,%2,%3}, {%4,%5,%6,%7}, {%8,%9}, {%0,%1,%2,%3};"
                 : "+f"(d[0]), "+f"(d[1]), "+f"(d[2]), "+f"(d[3])
                 : "r"(a[0]), "r"(a[1]), "r"(a[2]), "r"(a[3]), "r"(b0), "r"(b1));
}

__device__ __forceinline__ void cp16(uint32_t s, const void* g) {
    asm volatile("cp.async.cg.shared.global [%0], [%1], 16;" :: "r"(s), "l"(g));
}
#define CP_COMMIT() asm volatile("cp.async.commit_group;" ::: "memory")
template <int N>
__device__ __forceinline__ void cp_wait() {
    asm volatile("cp.async.wait_group %0;" :: "n"(N) : "memory");
}

// ---------------------------------------------------------------------------
// CSR build: zero -> count -> scan (3 kernels) -> fill
// ---------------------------------------------------------------------------
__global__ void zero_cnt() {
    int tid = blockIdx.x * blockDim.x + threadIdx.x;
    int stride = gridDim.x * blockDim.x;
    for (int i = tid; i < NN; i += stride) g_cnt[i] = 0;
}

__global__ void count_deg(const int* __restrict__ ei) {
    int tid = blockIdx.x * blockDim.x + threadIdx.x;
    int stride = gridDim.x * blockDim.x;
    for (int e = tid; e < EE; e += stride)
        atomicAdd(&g_cnt[ei[EE + e]], 1);
}

__global__ void scan1() {   // grid = NCHUNK, 1024 threads
    __shared__ int wsum[32];
    int c = blockIdx.x, t = threadIdx.x;
    int i = c * 1024 + t;
    int v = (i < NN) ? g_cnt[i] : 0;
    int x = v;
#pragma unroll
    for (int o = 1; o < 32; o <<= 1) {
        int y = __shfl_up_sync(~0u, x, o);
        if ((t & 31) >= o) x += y;
    }
    if ((t & 31) == 31) wsum[t >> 5] = x;
    __syncthreads();
    if (t < 32) {
        int s = wsum[t];
#pragma unroll
        for (int o = 1; o < 32; o <<= 1) {
            int y = __shfl_up_sync(~0u, s, o);
            if (t >= o) s += y;
        }
        wsum[t] = s;
    }
    __syncthreads();
    int base = (t >= 32) ? wsum[(t >> 5) - 1] : 0;
    int incl = x + base;
    if (i < NN) g_off[i] = incl - v;
    if (t == 1023) g_chunksum[c] = incl;
}

__global__ void scan2() {   // 1 block, 128 threads
    __shared__ int ws[4];
    int t = threadIdx.x;
    int v = (t < NCHUNK) ? g_chunksum[t] : 0;
    int x = v;
#pragma unroll
    for (int o = 1; o < 32; o <<= 1) {
        int y = __shfl_up_sync(~0u, x, o);
        if ((t & 31) >= o) x += y;
    }
    if ((t & 31) == 31) ws[t >> 5] = x;
    __syncthreads();
    if (t < 4) {
        int s = ws[t];
#pragma unroll
        for (int o = 1; o < 4; o <<= 1) {
            int y = __shfl_up_sync(0xFu, s, o);
            if (t >= o) s += y;
        }
        ws[t] = s;
    }
    __syncthreads();
    int base = (t >= 32) ? ws[(t >> 5) - 1] : 0;
    if (t < NCHUNK) g_chunksum[t] = x + base - v;
}

__global__ void scan3() {
    int tid = blockIdx.x * blockDim.x + threadIdx.x;
    int stride = gridDim.x * blockDim.x;
    for (int i = tid; i < NN; i += stride) {
        int o = g_off[i] + g_chunksum[i >> 10];
        g_off[i] = o;
        g_pos[i] = o;
    }
}

__global__ void fill_csr(const int* __restrict__ ei) {
    int tid = blockIdx.x * blockDim.x + threadIdx.x;
    int stride = gridDim.x * blockDim.x;
    for (int e = tid; e < EE; e += stride) {
        int d = ei[EE + e];
        int p = atomicAdd(&g_pos[d], 1);
        g_csr[p] = ei[e];
    }
}

// ---------------------------------------------------------------------------
// Pre-split weights, [n][k] layout.
// ---------------------------------------------------------------------------
__global__ void prep_weights(const float* __restrict__ W1l, const float* __restrict__ W1r,
                             const float* __restrict__ W2l, const float* __restrict__ W2r) {
    int idx = blockIdx.x * blockDim.x + threadIdx.x;
    if (idx < 128 * 256) {
        int n = idx >> 8, k = idx & 255;
        float v = (k < 128) ? W1l[n * 128 + k] : W1r[n * 128 + (k - 128)];
        __nv_bfloat16 h, l; split2(v, h, l);
        g_B1hi[idx] = h; g_B1lo[idx] = l;
    }
    int idx2 = idx - 128 * 256;
    if (idx2 >= 0 && idx2 < 128 * 128) {
        int n = idx2 >> 7, k = idx2 & 127;
        float v = (n < 64) ? W2l[n * 128 + k] : W2r[(n - 64) * 128 + k];
        __nv_bfloat16 h, l; split2(v, h, l);
        g_B2hi[idx2] = h; g_B2lo[idx2] = l;
    }
}

// ---------------------------------------------------------------------------
// gather1: warp per node. Sum x[src] over CSR range, mean, split -> A1 planes
// cols [0,128); split x[i] -> A1 planes cols [128,256).
// ---------------------------------------------------------------------------
__global__ void gather1(const float4* __restrict__ x4) {
    int lane = threadIdx.x & 31;
    int gw = (blockIdx.x * blockDim.x + threadIdx.x) >> 5;
    int nw = (gridDim.x * blockDim.x) >> 5;
    for (int i = gw; i < NN; i += nw) {
        int deg = g_cnt[i], start = g_off[i];
        float4 acc = make_float4(0.f, 0.f, 0.f, 0.f);
        int j = 0;
        for (; j + 4 <= deg; j += 4) {
            int s0 = g_csr[start + j], s1 = g_csr[start + j + 1];
            int s2 = g_csr[start + j + 2], s3 = g_csr[start + j + 3];
            float4 v0 = x4[s0 * 32 + lane];
            float4 v1 = x4[s1 * 32 + lane];
            float4 v2 = x4[s2 * 32 + lane];
            float4 v3 = x4[s3 * 32 + lane];
            acc.x += (v0.x + v1.x) + (v2.x + v3.x);
            acc.y += (v0.y + v1.y) + (v2.y + v3.y);
            acc.z += (v0.z + v1.z) + (v2.z + v3.z);
            acc.w += (v0.w + v1.w) + (v2.w + v3.w);
        }
        for (; j < deg; j++) {
            int s = g_csr[start + j];
            float4 v = x4[s * 32 + lane];
            acc.x += v.x; acc.y += v.y; acc.z += v.z; acc.w += v.w;
        }
        float inv = 1.0f / fmaxf((float)deg, 1.0f);
        acc.x *= inv; acc.y *= inv; acc.z *= inv; acc.w *= inv;
        __nv_bfloat16 h0, h1, h2, h3, l0, l1, l2, l3;
        split2(acc.x, h0, l0); split2(acc.y, h1, l1);
        split2(acc.z, h2, l2); split2(acc.w, h3, l3);
        uint2 uh, ul;
        uh.x = pack_bf(h0, h1); uh.y = pack_bf(h2, h3);
        ul.x = pack_bf(l0, l1); ul.y = pack_bf(l2, l3);
        ((uint2*)g_A1hi)[(size_t)i * 64 + lane] = uh;
        ((uint2*)g_A1lo)[(size_t)i * 64 + lane] = ul;
        // x part -> cols 128..255
        float4 xv = x4[i * 32 + lane];
        split2(xv.x, h0, l0); split2(xv.y, h1, l1);
        split2(xv.z, h2, l2); split2(xv.w, h3, l3);
        uh.x = pack_bf(h0, h1); uh.y = pack_bf(h2, h3);
        ul.x = pack_bf(l0, l1); ul.y = pack_bf(l2, l3);
        ((uint2*)g_A1hi)[(size_t)i * 64 + 32 + lane] = uh;
        ((uint2*)g_A1lo)[(size_t)i * 64 + 32 + lane] = ul;
    }
}

// ---------------------------------------------------------------------------
// gather2 (+ fused finalize): warp per node, lane owns 2 of 64 cols.
// out[i] = mean_j(y[src_j]) + b2 + y2[i]
// ---------------------------------------------------------------------------
__global__ void gather2(float* __restrict__ out, const float* __restrict__ b2) {
    int lane = threadIdx.x & 31;
    int gw = (blockIdx.x * blockDim.x + threadIdx.x) >> 5;
    int nw = (gridDim.x * blockDim.x) >> 5;
    const float2* __restrict__ z2 = (const float2*)g_z;
    for (int i = gw; i < NN; i += nw) {
        int deg = g_cnt[i], start = g_off[i];
        float2 acc = make_float2(0.f, 0.f);
        int j = 0;
        for (; j + 4 <= deg; j += 4) {
            int s0 = g_csr[start + j], s1 = g_csr[start + j + 1];
            int s2 = g_csr[start + j + 2], s3 = g_csr[start + j + 3];
            float2 v0 = z2[(size_t)s0 * 64 + lane];
            float2 v1 = z2[(size_t)s1 * 64 + lane];
            float2 v2 = z2[(size_t)s2 * 64 + lane];
            float2 v3 = z2[(size_t)s3 * 64 + lane];
            acc.x += (v0.x + v1.x) + (v2.x + v3.x);
            acc.y += (v0.y + v1.y) + (v2.y + v3.y);
        }
        for (; j < deg; j++) {
            int s = g_csr[start + j];
            float2 v = z2[(size_t)s * 64 + lane];
            acc.x += v.x; acc.y += v.y;
        }
        float inv = 1.0f / fmaxf((float)deg, 1.0f);
        float2 y2 = z2[(size_t)i * 64 + 32 + lane];
        float2 bb = ((const float2*)b2)[lane];
        float2 o = make_float2(acc.x * inv + bb.x + y2.x,
                               acc.y * inv + bb.y + y2.y);
        ((float2*)out)[(size_t)i * 32 + lane] = o;
    }
}

// ---------------------------------------------------------------------------
// mma.sync split-bf16 GEMM (unchanged from R4). 512 threads, tile 128x128.
// ---------------------------------------------------------------------------
template <int MODE>
__global__ __launch_bounds__(512, 1)
void gemm_mma(const float* __restrict__ b1) {
    constexpr int KTOT = (MODE == 0) ? 256 : 128;
    constexpr int CH   = KTOT / 64;
    constexpr int A_HI = 0, A_LO = 16384, B_HI = 32768, B_LO = 49152;
    extern __shared__ char sm[];
    const uint32_t sb = smem_u32(sm);
    const int tid = threadIdx.x, wid = tid >> 5, lane = tid & 31;
    const int rowBase = blockIdx.x * 128;
    const int wm = wid & 3, wn = wid >> 2;
    const int sub = lane >> 3, lr = lane & 7;

    const __nv_bfloat16* __restrict__ Ah = (MODE == 0) ? g_A1hi : g_h_hi;
    const __nv_bfloat16* __restrict__ Al = (MODE == 0) ? g_A1lo : g_h_lo;
    const __nv_bfloat16* __restrict__ Bh = (MODE == 0) ? g_B1hi : g_B2hi;
    const __nv_bfloat16* __restrict__ Bl = (MODE == 0) ? g_B1lo : g_B2lo;

    auto load_chunk = [&](int c, int buf) {
        const uint32_t bb = sb + buf * 65536;
#pragma unroll
        for (int it = 0; it < 2; it++) {
            int idx = it * 512 + tid;
            int row = idx >> 3, seg = idx & 7;
            uint32_t doff = SWZ((uint32_t)(row * 128 + seg * 16));
            size_t ga = (size_t)(rowBase + row) * KTOT + c * 64 + seg * 8;
            cp16(bb + A_HI + doff, Ah + ga);
            cp16(bb + A_LO + doff, Al + ga);
            size_t gb = (size_t)row * KTOT + c * 64 + seg * 8;
            cp16(bb + B_HI + doff, Bh + gb);
            cp16(bb + B_LO + doff, Bl + gb);
        }
    };

    float acc[2][4][4];
#pragma unroll
    for (int i = 0; i < 2; i++)
#pragma unroll
        for (int j = 0; j < 4; j++)
#pragma unroll
            for (int r = 0; r < 4; r++) acc[i][j][r] = 0.f;

    load_chunk(0, 0); CP_COMMIT();

    for (int c = 0; c < CH; c++) {
        if (c + 1 < CH) { load_chunk(c + 1, (c + 1) & 1); CP_COMMIT(); cp_wait<1>(); }
        else            { cp_wait<0>(); }
        __syncthreads();

        const uint32_t bb = sb + (c & 1) * 65536;
#pragma unroll
        for (int kk = 0; kk < 4; kk++) {
            uint32_t ah[2][4], al[2][4];
#pragma unroll
            for (int mi = 0; mi < 2; mi++) {
                int row = wm * 32 + mi * 16 + (sub & 1) * 8 + lr;
                int kb  = kk * 32 + (sub >> 1) * 16;
                uint32_t off = SWZ((uint32_t)(row * 128 + kb));
                LDSM4(ah[mi], bb + A_HI + off);
                LDSM4(al[mi], bb + A_LO + off);
            }
#pragma unroll
            for (int p = 0; p < 2; p++) {
                int nr = wn * 32 + p * 16 + (sub >> 1) * 8 + lr;
                int kb = kk * 32 + (sub & 1) * 16;
                uint32_t off = SWZ((uint32_t)(nr * 128 + kb));
                uint32_t bh[4], bl[4];
                LDSM4(bh, bb + B_HI + off);
                LDSM4(bl, bb + B_LO + off);
#pragma unroll
                for (int mi = 0; mi < 2; mi++) {
#pragma unroll
                    for (int h = 0; h < 2; h++) {
                        float* d = acc[mi][p * 2 + h];
                        mma_bf16(d, ah[mi], bh[2 * h], bh[2 * h + 1]);
                        mma_bf16(d, al[mi], bh[2 * h], bh[2 * h + 1]);
                        mma_bf16(d, ah[mi], bl[2 * h], bl[2 * h + 1]);
                    }
                }
            }
        }
        __syncthreads();
    }

#pragma unroll
    for (int mi = 0; mi < 2; mi++) {
        int r0 = rowBase + wm * 32 + mi * 16 + (lane >> 2);
#pragma unroll
        for (int p = 0; p < 2; p++) {
#pragma unroll
            for (int h = 0; h < 2; h++) {
                int col = wn * 32 + p * 16 + h * 8 + 2 * (lane & 3);
                float* d = acc[mi][p * 2 + h];
#pragma unroll
                for (int half = 0; half < 2; half++) {
                    int gr = r0 + half * 8;
                    if (gr < NN) {
                        float v0 = d[half * 2 + 0];
                        float v1 = d[half * 2 + 1];
                        if (MODE == 0) {
                            v0 = fmaxf(v0 + b1[col], 0.f);
                            v1 = fmaxf(v1 + b1[col + 1], 0.f);
                            __nv_bfloat16 h0, l0, h1, l1;
                            split2(v0, h0, l0); split2(v1, h1, l1);
                            *(uint32_t*)(g_h_hi + (size_t)gr * 128 + col) = pack_bf(h0, h1);
                            *(uint32_t*)(g_h_lo + (size_t)gr * 128 + col) = pack_bf(l0, l1);
                        } else {
                            *(float2*)(g_z + (size_t)gr * 128 + col) = make_float2(v0, v1);
                        }
                    }
                }
            }
        }
    }
}

// ---------------------------------------------------------------------------
// Launch. Inputs: x, W1_l, W1_r, b1, W2_l, W2_r, b2, edge_index
// ---------------------------------------------------------------------------
extern "C" void kernel_launch(void* const* d_in, const int* in_sizes, int n_in,
                              void* d_out, int out_size) {
    const float* x   = (const float*)d_in[0];
    const float* W1l = (const float*)d_in[1];
    const float* W1r = (const float*)d_in[2];
    const float* b1  = (const float*)d_in[3];
    const float* W2l = (const float*)d_in[4];
    const float* W2r = (const float*)d_in[5];
    const float* b2  = (const float*)d_in[6];
    const int*   ei  = (const int*)d_in[7];
    float* out = (float*)d_out;

    const int SMEM = 2 * 65536;  // 128 KB
    cudaFuncSetAttribute(gemm_mma<0>, cudaFuncAttributeMaxDynamicSharedMemorySize, SMEM);
    cudaFuncSetAttribute(gemm_mma<1>, cudaFuncAttributeMaxDynamicSharedMemorySize, SMEM);

    const int NBLK = (NN + 127) / 128;  // 782

    // CSR build
    zero_cnt<<<256, 256>>>();
    prep_weights<<<192, 256>>>(W1l, W1r, W2l, W2r);
    count_deg<<<2048, 256>>>(ei);
    scan1<<<NCHUNK, 1024>>>();
    scan2<<<1, 128>>>();
    scan3<<<392, 256>>>();
    fill_csr<<<2048, 256>>>(ei);
    // Layer 1
    gather1<<<2048, 256>>>((const float4*)x);
    gemm_mma<0><<<NBLK, 512, SMEM>>>(b1);
    // Layer 2
    gemm_mma<1><<<NBLK, 512, SMEM>>>(b1);
    gather2<<<2048, 256>>>(out, b2);
}